// round 5
// baseline (speedup 1.0000x reference)
#include <cuda_runtime.h>
#include <math.h>

// Problem constants
#define HD   512
#define BB   64
#define TT   512
#define FUT  96
#define FF   64
#define NB   128      // persistent CTAs (1 per SM, 128 <= 148 SMs -> co-resident)

typedef unsigned long long u64;

// ---------------------------------------------------------------------------
// Persistent device state. h/c stored TRANSPOSED [j][b] (coalesced, lanes=b).
// ---------------------------------------------------------------------------
__device__ float g_h0[2][HD * BB];
__device__ float g_h1[2][HD * BB];
__device__ float g_c0[HD * BB];
__device__ float g_c1[HD * BB];
__device__ float g_decx[FF * BB];        // decoder feedback, transposed [f][b]

__device__ unsigned g_bar_cnt;           // zero-initialized
__device__ unsigned g_bar_gen;

// ---------------------------------------------------------------------------
// Packed f32x2 FMA: 2 FMA lanes per issue slot (FFMA 3-reg is rt=2 on B300).
// ---------------------------------------------------------------------------
__device__ __forceinline__ void fma2(u64 &acc, u64 a, u64 b) {
    asm("fma.rn.f32x2 %0, %1, %2, %0;" : "+l"(acc) : "l"(a), "l"(b));
}
__device__ __forceinline__ float unpack_sum(u64 a) {
    float lo, hi;
    asm("mov.b64 {%0,%1}, %2;" : "=f"(lo), "=f"(hi) : "l"(a));
    return lo + hi;
}
__device__ __forceinline__ float sigm(float x) { return 1.0f / (1.0f + expf(-x)); }

// ---------------------------------------------------------------------------
// Grid-wide barrier (sense-reversing; mirrors cooperative-groups grid.sync).
// Safe: all NB CTAs are resident simultaneously.
// ---------------------------------------------------------------------------
__device__ __forceinline__ void gbar() {
    __syncthreads();
    if (threadIdx.x == 0) {
        unsigned gen = *(volatile unsigned*)&g_bar_gen;  // read BEFORE arrive
        __threadfence();                                  // release this CTA's writes
        unsigned arrived = atomicAdd(&g_bar_cnt, 1u);
        if (arrived == NB - 1) {
            atomicExch(&g_bar_cnt, 0u);
            __threadfence();
            *(volatile unsigned*)&g_bar_gen = gen + 1u;
        } else {
            while (*(volatile unsigned*)&g_bar_gen == gen) { }
            __threadfence();                              // acquire others' writes
        }
    }
    __syncthreads();
}

// ---------------------------------------------------------------------------
// Staging: transposed source [k][64] -> regs -> xs[b][k] (stride 68 floats,
// conflict-free for LDS.128 with lanes = b). Split ld/st for SW pipelining.
// ---------------------------------------------------------------------------
__device__ __forceinline__ void stage_ld(float2 r[8], const float* __restrict__ src, int k0) {
    int w = threadIdx.x >> 5, lane = threadIdx.x & 31;
    const float* p = src + (size_t)(k0 + w * 8) * 64 + lane * 2;
#pragma unroll
    for (int kk = 0; kk < 8; kk++) r[kk] = *(const float2*)(p + kk * 64);
}
__device__ __forceinline__ void stage_st(const float2 r[8], float* xs) {
    int w = threadIdx.x >> 5, lane = threadIdx.x & 31;
    int b0 = lane * 2, kb = w * 8;
    *(float4*)(xs + (size_t)b0 * 68 + kb)           = make_float4(r[0].x, r[1].x, r[2].x, r[3].x);
    *(float4*)(xs + (size_t)b0 * 68 + kb + 4)       = make_float4(r[4].x, r[5].x, r[6].x, r[7].x);
    *(float4*)(xs + (size_t)(b0 + 1) * 68 + kb)     = make_float4(r[0].y, r[1].y, r[2].y, r[3].y);
    *(float4*)(xs + (size_t)(b0 + 1) * 68 + kb + 4) = make_float4(r[4].y, r[5].y, r[6].y, r[7].y);
}
// Row-major source (input_seq row = 64 floats, row stride 32768)
__device__ __forceinline__ void stage_R(float* xs, const float* __restrict__ src) {
    for (int i = threadIdx.x; i < 1024; i += 256) {
        int b = i >> 4, q = i & 15;
        float4 v = *(const float4*)(src + (size_t)b * (TT * FF) + q * 4);
        *(float4*)(xs + (size_t)b * 68 + q * 4) = v;
    }
}

// ---------------------------------------------------------------------------
// 64-k chunk of the 4-gate dot products. x from smem (vec, conflict-free),
// w from smem (warp-uniform -> broadcast).
// ---------------------------------------------------------------------------
__device__ __forceinline__ void acc64(u64 acc[4], const float* xrow,
                                      const float* w0, const float* w1,
                                      const float* w2, const float* w3) {
#pragma unroll
    for (int k = 0; k < 64; k += 4) {
        ulonglong2 xv = *(const ulonglong2*)(xrow + k);
        ulonglong2 wv;
        wv = *(const ulonglong2*)(w0 + k); fma2(acc[0], xv.x, wv.x); fma2(acc[0], xv.y, wv.y);
        wv = *(const ulonglong2*)(w1 + k); fma2(acc[1], xv.x, wv.x); fma2(acc[1], xv.y, wv.y);
        wv = *(const ulonglong2*)(w2 + k); fma2(acc[2], xv.x, wv.x); fma2(acc[2], xv.y, wv.y);
        wv = *(const ulonglong2*)(w3 + k); fma2(acc[3], xv.x, wv.x); fma2(acc[3], xv.y, wv.y);
    }
}

// K=512 part, software-pipelined: prefetch chunk c+1 into regs during acc of c.
__device__ __forceinline__ void acc_part512(u64 acc[4], const float* __restrict__ src,
                                            const float* ws, float* xs, int b, int jj) {
    float2 r[8];
    stage_ld(r, src, 0);
#pragma unroll 1
    for (int c = 0; c < 8; c++) {
        __syncthreads();
        stage_st(r, xs);
        __syncthreads();
        if (c < 7) stage_ld(r, src, (c + 1) * 64);
        int k0 = c * 64;
        acc64(acc, xs + (size_t)b * 68,
              ws + (size_t)(jj)      * 512 + k0,
              ws + (size_t)(4  + jj) * 512 + k0,
              ws + (size_t)(8  + jj) * 512 + k0,
              ws + (size_t)(12 + jj) * 512 + k0);
    }
}

// ---------------------------------------------------------------------------
// Full LSTM cell for this thread's (b, j): gates + nonlinearity + c/h update.
// Exactly one of xT (transposed [k][64]) / xR (row-major) is non-null for the
// input projection; KIN is 64 or 512.
// ---------------------------------------------------------------------------
__device__ __noinline__ void lstm_cell(const float* Wih, int KIN, const float* Whh,
                                       const float* __restrict__ xT,
                                       const float* __restrict__ xR,
                                       const float* __restrict__ hprev,
                                       float* __restrict__ hnext,
                                       float* __restrict__ cbuf,
                                       float* xs, float4 bias, int b, int jj, int j) {
    u64 acc[4] = {0ull, 0ull, 0ull, 0ull};
    if (KIN == 64) {
        __syncthreads();
        if (xR) {
            stage_R(xs, xR);
        } else {
            float2 r[8];
            stage_ld(r, xT, 0);
            stage_st(r, xs);
        }
        __syncthreads();
        acc64(acc, xs + (size_t)b * 68,
              Wih + (size_t)(jj)      * 64,
              Wih + (size_t)(4  + jj) * 64,
              Wih + (size_t)(8  + jj) * 64,
              Wih + (size_t)(12 + jj) * 64);
    } else {
        acc_part512(acc, xT, Wih, xs, b, jj);
    }
    acc_part512(acc, hprev, Whh, xs, b, jj);

    float gi = unpack_sum(acc[0]) + bias.x;
    float gf = unpack_sum(acc[1]) + bias.y;
    float gg = unpack_sum(acc[2]) + bias.z;
    float go = unpack_sum(acc[3]) + bias.w;

    int idx = j * 64 + b;
    float c = sigm(gf) * cbuf[idx] + sigm(gi) * tanhf(gg);
    cbuf[idx]  = c;
    hnext[idx] = sigm(go) * tanhf(c);
}

// Decoder FC for CTA f (< 64): out[:,d,f] = h1 @ fcrow + fcb[f]; also g_decx.
__device__ __noinline__ void fc_step(const float* fcrow, float fcbias,
                                     const float* __restrict__ h1,
                                     float* __restrict__ out, int d, float* xs, int f) {
    int b = threadIdx.x & 63, q = threadIdx.x >> 6;
    u64 acc = 0ull;
    float2 r[8];
    stage_ld(r, h1, 0);
#pragma unroll 1
    for (int c = 0; c < 8; c++) {
        __syncthreads();
        stage_st(r, xs);
        __syncthreads();
        if (c < 7) stage_ld(r, h1, (c + 1) * 64);
        const float* xrow = xs + (size_t)b * 68 + q * 16;
        const float* w    = fcrow + c * 64 + q * 16;
#pragma unroll
        for (int k = 0; k < 16; k += 4) {
            ulonglong2 xv = *(const ulonglong2*)(xrow + k);
            ulonglong2 wv = *(const ulonglong2*)(w + k);
            fma2(acc, xv.x, wv.x); fma2(acc, xv.y, wv.y);
        }
    }
    __syncthreads();
    xs[q * 64 + b] = unpack_sum(acc);
    __syncthreads();
    if (q == 0) {
        float v = xs[b] + xs[64 + b] + xs[128 + b] + xs[192 + b] + fcbias;
        out[(size_t)b * (FUT * FF) + (size_t)d * FF + f] = v;
        g_decx[f * 64 + b] = v;
    }
}

// Copy this CTA's 16 weight rows (4 gates x 4 j) for one matrix into smem.
__device__ __forceinline__ void loadW(float* dst, const float* __restrict__ src,
                                      int K, int j0) {
    int Kq = K >> 2;
    int n = 16 * Kq;
    for (int i = threadIdx.x; i < n; i += 256) {
        int rr = i / Kq, kq = i - rr * Kq;
        int g = rr >> 2, jj2 = rr & 3;
        float4 v = *(const float4*)(src + (size_t)(g * HD + j0 + jj2) * K + kq * 4);
        *(float4*)(dst + (size_t)rr * K + kq * 4) = v;
    }
}

// ---------------------------------------------------------------------------
// ONE persistent kernel = the entire seq2seq network.
// SMEM (floats): 8 weight slices (51200) + fc row (512) + xs (64*68=4352)
// ---------------------------------------------------------------------------
__global__ void __launch_bounds__(256, 1)
lstm_persist(const float* __restrict__ in,
             const float* __restrict__ eWih0, const float* __restrict__ eWhh0,
             const float* __restrict__ ebih0, const float* __restrict__ ebhh0,
             const float* __restrict__ eWih1, const float* __restrict__ eWhh1,
             const float* __restrict__ ebih1, const float* __restrict__ ebhh1,
             const float* __restrict__ dWih0, const float* __restrict__ dWhh0,
             const float* __restrict__ dbih0, const float* __restrict__ dbhh0,
             const float* __restrict__ dWih1, const float* __restrict__ dWhh1,
             const float* __restrict__ dbih1, const float* __restrict__ dbhh1,
             const float* __restrict__ fcW,   const float* __restrict__ fcb,
             float* __restrict__ out) {
    extern __shared__ float sm[];
    float* eW0i = sm;            // 1024
    float* eW0h = sm + 1024;     // 8192
    float* eW1i = sm + 9216;     // 8192
    float* eW1h = sm + 17408;    // 8192
    float* dW0i = sm + 25600;    // 1024
    float* dW0h = sm + 26624;    // 8192
    float* dW1i = sm + 34816;    // 8192
    float* dW1h = sm + 43008;    // 8192
    float* fcrow = sm + 51200;   // 512
    float* xs    = sm + 51712;   // 4352

    const int tid = threadIdx.x;
    const int b = tid & 63, jj = tid >> 6;
    const int j0 = blockIdx.x * 4, j = j0 + jj;

    // One-time loads: weights -> smem
    loadW(eW0i, eWih0, 64, j0);
    loadW(eW0h, eWhh0, HD, j0);
    loadW(eW1i, eWih1, HD, j0);
    loadW(eW1h, eWhh1, HD, j0);
    loadW(dW0i, dWih0, 64, j0);
    loadW(dW0h, dWhh0, HD, j0);
    loadW(dW1i, dWih1, HD, j0);
    loadW(dW1h, dWhh1, HD, j0);
    float fcbias = 0.f;
    if (blockIdx.x < 64) {
        for (int i = tid; i < HD; i += 256) fcrow[i] = fcW[(size_t)blockIdx.x * HD + i];
        fcbias = fcb[blockIdx.x];
    }

    // Zero persistent state (exactly one element per thread)
    {
        int i = blockIdx.x * 256 + tid;          // [0, 32768)
        g_h0[0][i] = 0.f; g_h1[0][i] = 0.f;
        g_c0[i] = 0.f;    g_c1[i] = 0.f;
        if (i < FF * BB) g_decx[i] = 0.f;
    }

    // Combined biases for this thread's j (gate order: i, f, g, o)
    float4 b_e0 = make_float4(ebih0[j] + ebhh0[j],
                              ebih0[HD + j] + ebhh0[HD + j],
                              ebih0[2 * HD + j] + ebhh0[2 * HD + j],
                              ebih0[3 * HD + j] + ebhh0[3 * HD + j]);
    float4 b_e1 = make_float4(ebih1[j] + ebhh1[j],
                              ebih1[HD + j] + ebhh1[HD + j],
                              ebih1[2 * HD + j] + ebhh1[2 * HD + j],
                              ebih1[3 * HD + j] + ebhh1[3 * HD + j]);
    float4 b_d0 = make_float4(dbih0[j] + dbhh0[j],
                              dbih0[HD + j] + dbhh0[HD + j],
                              dbih0[2 * HD + j] + dbhh0[2 * HD + j],
                              dbih0[3 * HD + j] + dbhh0[3 * HD + j]);
    float4 b_d1 = make_float4(dbih1[j] + dbhh1[j],
                              dbih1[HD + j] + dbhh1[HD + j],
                              dbih1[2 * HD + j] + dbhh1[2 * HD + j],
                              dbih1[3 * HD + j] + dbhh1[3 * HD + j]);

    gbar();   // zeros visible everywhere

    // ===================== encoder =====================
    // L0(t): reads g_h0[t&1], writes g_h0[(t&1)^1]
    // L1(t): x = g_h0[(t+1)&1], reads g_h1[t&1], writes g_h1[(t&1)^1]
    lstm_cell(eW0i, 64, eW0h, nullptr, in /* t=0 row */, g_h0[0], g_h0[1], g_c0,
              xs, b_e0, b, jj, j);
    gbar();
#pragma unroll 1
    for (int t = 0; t < TT - 1; t++) {
        int s = t & 1;
        // phase: L1(t) and L0(t+1) are independent -> one barrier per timestep
        lstm_cell(eW1i, HD, eW1h, g_h0[s ^ 1], nullptr, g_h1[s], g_h1[s ^ 1], g_c1,
                  xs, b_e1, b, jj, j);
        lstm_cell(eW0i, 64, eW0h, nullptr, in + (size_t)(t + 1) * FF,
                  g_h0[s ^ 1], g_h0[s], g_c0, xs, b_e0, b, jj, j);
        gbar();
    }
    {
        int s = (TT - 1) & 1;   // = 1
        lstm_cell(eW1i, HD, eW1h, g_h0[s ^ 1], nullptr, g_h1[s], g_h1[s ^ 1], g_c1,
                  xs, b_e1, b, jj, j);
    }
    gbar();
    // encoder end: current h0 = slot 0, current h1 = slot 0

    // ===================== decoder =====================
#pragma unroll 1
    for (int d = 0; d < FUT; d++) {
        int p = d & 1;
        if (d == 0)
            lstm_cell(dW0i, 64, dW0h, nullptr, in + (size_t)(TT - 1) * FF,
                      g_h0[p], g_h0[p ^ 1], g_c0, xs, b_d0, b, jj, j);
        else
            lstm_cell(dW0i, 64, dW0h, g_decx, nullptr,
                      g_h0[p], g_h0[p ^ 1], g_c0, xs, b_d0, b, jj, j);
        gbar();
        lstm_cell(dW1i, HD, dW1h, g_h0[p ^ 1], nullptr,
                  g_h1[p], g_h1[p ^ 1], g_c1, xs, b_d1, b, jj, j);
        gbar();
        if (blockIdx.x < 64)
            fc_step(fcrow, fcbias, g_h1[p ^ 1], out, d, xs, blockIdx.x);
        gbar();
    }
}

// ---------------------------------------------------------------------------
// Host: ONE launch -> 1 graph node, no multi-node upload buffer.
// ---------------------------------------------------------------------------
extern "C" void kernel_launch(void* const* d_in, const int* in_sizes, int n_in,
                              void* d_out, int out_size) {
    const size_t SMEM = 56064 * sizeof(float);   // 224,256 B <= 227 KB opt-in
    cudaFuncSetAttribute(lstm_persist, cudaFuncAttributeMaxDynamicSharedMemorySize,
                         (int)SMEM);

    lstm_persist<<<NB, 256, SMEM>>>(
        (const float*)d_in[0],
        (const float*)d_in[1],  (const float*)d_in[2],
        (const float*)d_in[3],  (const float*)d_in[4],
        (const float*)d_in[5],  (const float*)d_in[6],
        (const float*)d_in[7],  (const float*)d_in[8],
        (const float*)d_in[9],  (const float*)d_in[10],
        (const float*)d_in[11], (const float*)d_in[12],
        (const float*)d_in[13], (const float*)d_in[14],
        (const float*)d_in[15], (const float*)d_in[16],
        (const float*)d_in[17], (const float*)d_in[18],
        (float*)d_out);
}

// round 6
// speedup vs baseline: 1.0478x; 1.0478x over previous
#include <cuda_runtime.h>
#include <math.h>

// Problem constants
#define HD   512
#define BB   64
#define TT   512
#define FUT  96
#define FF   64
#define NB   128      // persistent CTAs (1 per SM, 128 <= 148 SMs -> co-resident)

typedef unsigned long long u64;

// ---------------------------------------------------------------------------
// Persistent device state. h/c stored TRANSPOSED [j][b] (coalesced, lanes=b).
// ---------------------------------------------------------------------------
__device__ float g_h0[2][HD * BB];
__device__ float g_h1[2][HD * BB];
__device__ float g_c0[HD * BB];
__device__ float g_c1[HD * BB];
__device__ float g_decx[FF * BB];        // decoder feedback, transposed [f][b]

__device__ unsigned g_bar_cnt;           // zero-initialized
__device__ unsigned g_bar_gen;

// ---------------------------------------------------------------------------
// Packed f32x2 FMA: 2 FMA lanes per issue slot (FFMA 3-reg is rt=2 on B300).
// ---------------------------------------------------------------------------
__device__ __forceinline__ void fma2(u64 &acc, u64 a, u64 b) {
    asm("fma.rn.f32x2 %0, %1, %2, %0;" : "+l"(acc) : "l"(a), "l"(b));
}
__device__ __forceinline__ float unpack_sum(u64 a) {
    float lo, hi;
    asm("mov.b64 {%0,%1}, %2;" : "=f"(lo), "=f"(hi) : "l"(a));
    return lo + hi;
}
__device__ __forceinline__ float sigm(float x) { return 1.0f / (1.0f + expf(-x)); }

// ---------------------------------------------------------------------------
// Grid-wide barrier (sense-reversing; mirrors cooperative-groups grid.sync).
// Safe: all NB CTAs are resident simultaneously.
// ---------------------------------------------------------------------------
__device__ __forceinline__ void gbar() {
    __syncthreads();
    if (threadIdx.x == 0) {
        unsigned gen = *(volatile unsigned*)&g_bar_gen;  // read BEFORE arrive
        __threadfence();                                  // release this CTA's writes
        unsigned arrived = atomicAdd(&g_bar_cnt, 1u);
        if (arrived == NB - 1) {
            atomicExch(&g_bar_cnt, 0u);
            __threadfence();
            *(volatile unsigned*)&g_bar_gen = gen + 1u;
        } else {
            while (*(volatile unsigned*)&g_bar_gen == gen) { }
            __threadfence();                              // acquire others' writes
        }
    }
    __syncthreads();
}

// ---------------------------------------------------------------------------
// Staging: transposed source [k][64] -> regs -> xs[b][k] (stride 68 floats,
// conflict-free for LDS.128 with lanes = b). Split ld/st for SW pipelining.
// ---------------------------------------------------------------------------
__device__ __forceinline__ void stage_ld(float2 r[8], const float* __restrict__ src, int k0) {
    int w = threadIdx.x >> 5, lane = threadIdx.x & 31;
    const float* p = src + (size_t)(k0 + w * 8) * 64 + lane * 2;
#pragma unroll
    for (int kk = 0; kk < 8; kk++) r[kk] = *(const float2*)(p + kk * 64);
}
__device__ __forceinline__ void stage_st(const float2 r[8], float* xs) {
    int w = threadIdx.x >> 5, lane = threadIdx.x & 31;
    int b0 = lane * 2, kb = w * 8;
    *(float4*)(xs + (size_t)b0 * 68 + kb)           = make_float4(r[0].x, r[1].x, r[2].x, r[3].x);
    *(float4*)(xs + (size_t)b0 * 68 + kb + 4)       = make_float4(r[4].x, r[5].x, r[6].x, r[7].x);
    *(float4*)(xs + (size_t)(b0 + 1) * 68 + kb)     = make_float4(r[0].y, r[1].y, r[2].y, r[3].y);
    *(float4*)(xs + (size_t)(b0 + 1) * 68 + kb + 4) = make_float4(r[4].y, r[5].y, r[6].y, r[7].y);
}
// Row-major source (input_seq row = 64 floats, row stride 32768)
__device__ __forceinline__ void stage_R(float* xs, const float* __restrict__ src) {
    for (int i = threadIdx.x; i < 1024; i += 256) {
        int b = i >> 4, q = i & 15;
        float4 v = *(const float4*)(src + (size_t)b * (TT * FF) + q * 4);
        *(float4*)(xs + (size_t)b * 68 + q * 4) = v;
    }
}

// ---------------------------------------------------------------------------
// 64-k chunk of the 4-gate dot products. x from smem (vec, conflict-free),
// w from smem (warp-uniform -> broadcast).
// ---------------------------------------------------------------------------
__device__ __forceinline__ void acc64(u64 acc[4], const float* xrow,
                                      const float* w0, const float* w1,
                                      const float* w2, const float* w3) {
#pragma unroll
    for (int k = 0; k < 64; k += 4) {
        ulonglong2 xv = *(const ulonglong2*)(xrow + k);
        ulonglong2 wv;
        wv = *(const ulonglong2*)(w0 + k); fma2(acc[0], xv.x, wv.x); fma2(acc[0], xv.y, wv.y);
        wv = *(const ulonglong2*)(w1 + k); fma2(acc[1], xv.x, wv.x); fma2(acc[1], xv.y, wv.y);
        wv = *(const ulonglong2*)(w2 + k); fma2(acc[2], xv.x, wv.x); fma2(acc[2], xv.y, wv.y);
        wv = *(const ulonglong2*)(w3 + k); fma2(acc[3], xv.x, wv.x); fma2(acc[3], xv.y, wv.y);
    }
}

// K=512 part, software-pipelined: prefetch chunk c+1 into regs during acc of c.
__device__ __forceinline__ void acc_part512(u64 acc[4], const float* __restrict__ src,
                                            const float* ws, float* xs, int b, int jj) {
    float2 r[8];
    stage_ld(r, src, 0);
#pragma unroll 1
    for (int c = 0; c < 8; c++) {
        __syncthreads();
        stage_st(r, xs);
        __syncthreads();
        if (c < 7) stage_ld(r, src, (c + 1) * 64);
        int k0 = c * 64;
        acc64(acc, xs + (size_t)b * 68,
              ws + (size_t)(jj)      * 512 + k0,
              ws + (size_t)(4  + jj) * 512 + k0,
              ws + (size_t)(8  + jj) * 512 + k0,
              ws + (size_t)(12 + jj) * 512 + k0);
    }
}

// ---------------------------------------------------------------------------
// Full LSTM cell for this thread's (b, j): gates + nonlinearity + c/h update.
// Exactly one of xT (transposed [k][64]) / xR (row-major) is non-null for the
// input projection; KIN is 64 or 512.
// ---------------------------------------------------------------------------
__device__ __noinline__ void lstm_cell(const float* Wih, int KIN, const float* Whh,
                                       const float* __restrict__ xT,
                                       const float* __restrict__ xR,
                                       const float* __restrict__ hprev,
                                       float* __restrict__ hnext,
                                       float* __restrict__ cbuf,
                                       float* xs, float4 bias, int b, int jj, int j) {
    u64 acc[4] = {0ull, 0ull, 0ull, 0ull};
    if (KIN == 64) {
        __syncthreads();
        if (xR) {
            stage_R(xs, xR);
        } else {
            float2 r[8];
            stage_ld(r, xT, 0);
            stage_st(r, xs);
        }
        __syncthreads();
        acc64(acc, xs + (size_t)b * 68,
              Wih + (size_t)(jj)      * 64,
              Wih + (size_t)(4  + jj) * 64,
              Wih + (size_t)(8  + jj) * 64,
              Wih + (size_t)(12 + jj) * 64);
    } else {
        acc_part512(acc, xT, Wih, xs, b, jj);
    }
    acc_part512(acc, hprev, Whh, xs, b, jj);

    float gi = unpack_sum(acc[0]) + bias.x;
    float gf = unpack_sum(acc[1]) + bias.y;
    float gg = unpack_sum(acc[2]) + bias.z;
    float go = unpack_sum(acc[3]) + bias.w;

    int idx = j * 64 + b;
    float c = sigm(gf) * cbuf[idx] + sigm(gi) * tanhf(gg);
    cbuf[idx]  = c;
    hnext[idx] = sigm(go) * tanhf(c);
}

// Decoder FC for CTA f (< 64): out[:,d,f] = h1 @ fcrow + fcb[f]; also g_decx.
__device__ __noinline__ void fc_step(const float* fcrow, float fcbias,
                                     const float* __restrict__ h1,
                                     float* __restrict__ out, int d, float* xs, int f) {
    int b = threadIdx.x & 63, q = threadIdx.x >> 6;
    u64 acc = 0ull;
    float2 r[8];
    stage_ld(r, h1, 0);
#pragma unroll 1
    for (int c = 0; c < 8; c++) {
        __syncthreads();
        stage_st(r, xs);
        __syncthreads();
        if (c < 7) stage_ld(r, h1, (c + 1) * 64);
        const float* xrow = xs + (size_t)b * 68 + q * 16;
        const float* w    = fcrow + c * 64 + q * 16;
#pragma unroll
        for (int k = 0; k < 16; k += 4) {
            ulonglong2 xv = *(const ulonglong2*)(xrow + k);
            ulonglong2 wv = *(const ulonglong2*)(w + k);
            fma2(acc, xv.x, wv.x); fma2(acc, xv.y, wv.y);
        }
    }
    __syncthreads();
    xs[q * 64 + b] = unpack_sum(acc);
    __syncthreads();
    if (q == 0) {
        float v = xs[b] + xs[64 + b] + xs[128 + b] + xs[192 + b] + fcbias;
        out[(size_t)b * (FUT * FF) + (size_t)d * FF + f] = v;
        g_decx[f * 64 + b] = v;
    }
}

// Copy this CTA's 16 weight rows (4 gates x 4 j) for one matrix into smem.
__device__ __forceinline__ void loadW(float* dst, const float* __restrict__ src,
                                      int K, int j0) {
    int Kq = K >> 2;
    int n = 16 * Kq;
    for (int i = threadIdx.x; i < n; i += 256) {
        int rr = i / Kq, kq = i - rr * Kq;
        int g = rr >> 2, jj2 = rr & 3;
        float4 v = *(const float4*)(src + (size_t)(g * HD + j0 + jj2) * K + kq * 4);
        *(float4*)(dst + (size_t)rr * K + kq * 4) = v;
    }
}

// ---------------------------------------------------------------------------
// ONE persistent kernel = the entire seq2seq network.
// SMEM (floats): 8 weight slices (51200) + fc row (512) + xs (64*68=4352)
// ---------------------------------------------------------------------------
__global__ void __launch_bounds__(256, 1)
lstm_persist(const float* __restrict__ in,
             const float* __restrict__ eWih0, const float* __restrict__ eWhh0,
             const float* __restrict__ ebih0, const float* __restrict__ ebhh0,
             const float* __restrict__ eWih1, const float* __restrict__ eWhh1,
             const float* __restrict__ ebih1, const float* __restrict__ ebhh1,
             const float* __restrict__ dWih0, const float* __restrict__ dWhh0,
             const float* __restrict__ dbih0, const float* __restrict__ dbhh0,
             const float* __restrict__ dWih1, const float* __restrict__ dWhh1,
             const float* __restrict__ dbih1, const float* __restrict__ dbhh1,
             const float* __restrict__ fcW,   const float* __restrict__ fcb,
             float* __restrict__ out) {
    extern __shared__ float sm[];
    float* eW0i = sm;            // 1024
    float* eW0h = sm + 1024;     // 8192
    float* eW1i = sm + 9216;     // 8192
    float* eW1h = sm + 17408;    // 8192
    float* dW0i = sm + 25600;    // 1024
    float* dW0h = sm + 26624;    // 8192
    float* dW1i = sm + 34816;    // 8192
    float* dW1h = sm + 43008;    // 8192
    float* fcrow = sm + 51200;   // 512
    float* xs    = sm + 51712;   // 4352

    const int tid = threadIdx.x;
    const int b = tid & 63, jj = tid >> 6;
    const int j0 = blockIdx.x * 4, j = j0 + jj;

    // One-time loads: weights -> smem
    loadW(eW0i, eWih0, 64, j0);
    loadW(eW0h, eWhh0, HD, j0);
    loadW(eW1i, eWih1, HD, j0);
    loadW(eW1h, eWhh1, HD, j0);
    loadW(dW0i, dWih0, 64, j0);
    loadW(dW0h, dWhh0, HD, j0);
    loadW(dW1i, dWih1, HD, j0);
    loadW(dW1h, dWhh1, HD, j0);
    float fcbias = 0.f;
    if (blockIdx.x < 64) {
        for (int i = tid; i < HD; i += 256) fcrow[i] = fcW[(size_t)blockIdx.x * HD + i];
        fcbias = fcb[blockIdx.x];
    }

    // Zero persistent state (exactly one element per thread)
    {
        int i = blockIdx.x * 256 + tid;          // [0, 32768)
        g_h0[0][i] = 0.f; g_h1[0][i] = 0.f;
        g_c0[i] = 0.f;    g_c1[i] = 0.f;
        if (i < FF * BB) g_decx[i] = 0.f;
    }

    // Combined biases for this thread's j (gate order: i, f, g, o)
    float4 b_e0 = make_float4(ebih0[j] + ebhh0[j],
                              ebih0[HD + j] + ebhh0[HD + j],
                              ebih0[2 * HD + j] + ebhh0[2 * HD + j],
                              ebih0[3 * HD + j] + ebhh0[3 * HD + j]);
    float4 b_e1 = make_float4(ebih1[j] + ebhh1[j],
                              ebih1[HD + j] + ebhh1[HD + j],
                              ebih1[2 * HD + j] + ebhh1[2 * HD + j],
                              ebih1[3 * HD + j] + ebhh1[3 * HD + j]);
    float4 b_d0 = make_float4(dbih0[j] + dbhh0[j],
                              dbih0[HD + j] + dbhh0[HD + j],
                              dbih0[2 * HD + j] + dbhh0[2 * HD + j],
                              dbih0[3 * HD + j] + dbhh0[3 * HD + j]);
    float4 b_d1 = make_float4(dbih1[j] + dbhh1[j],
                              dbih1[HD + j] + dbhh1[HD + j],
                              dbih1[2 * HD + j] + dbhh1[2 * HD + j],
                              dbih1[3 * HD + j] + dbhh1[3 * HD + j]);

    gbar();   // zeros visible everywhere

    // ===================== encoder =====================
    // L0(t): reads g_h0[t&1], writes g_h0[(t&1)^1]
    // L1(t): x = g_h0[(t+1)&1], reads g_h1[t&1], writes g_h1[(t&1)^1]
    lstm_cell(eW0i, 64, eW0h, nullptr, in /* t=0 row */, g_h0[0], g_h0[1], g_c0,
              xs, b_e0, b, jj, j);
    gbar();
#pragma unroll 1
    for (int t = 0; t < TT - 1; t++) {
        int s = t & 1;
        // phase: L1(t) and L0(t+1) are independent -> one barrier per timestep
        lstm_cell(eW1i, HD, eW1h, g_h0[s ^ 1], nullptr, g_h1[s], g_h1[s ^ 1], g_c1,
                  xs, b_e1, b, jj, j);
        lstm_cell(eW0i, 64, eW0h, nullptr, in + (size_t)(t + 1) * FF,
                  g_h0[s ^ 1], g_h0[s], g_c0, xs, b_e0, b, jj, j);
        gbar();
    }
    {
        int s = (TT - 1) & 1;   // = 1
        lstm_cell(eW1i, HD, eW1h, g_h0[s ^ 1], nullptr, g_h1[s], g_h1[s ^ 1], g_c1,
                  xs, b_e1, b, jj, j);
    }
    gbar();
    // encoder end: current h0 = slot 0, current h1 = slot 0

    // ===================== decoder =====================
#pragma unroll 1
    for (int d = 0; d < FUT; d++) {
        int p = d & 1;
        if (d == 0)
            lstm_cell(dW0i, 64, dW0h, nullptr, in + (size_t)(TT - 1) * FF,
                      g_h0[p], g_h0[p ^ 1], g_c0, xs, b_d0, b, jj, j);
        else
            lstm_cell(dW0i, 64, dW0h, g_decx, nullptr,
                      g_h0[p], g_h0[p ^ 1], g_c0, xs, b_d0, b, jj, j);
        gbar();
        lstm_cell(dW1i, HD, dW1h, g_h0[p ^ 1], nullptr,
                  g_h1[p], g_h1[p ^ 1], g_c1, xs, b_d1, b, jj, j);
        gbar();
        if (blockIdx.x < 64)
            fc_step(fcrow, fcbias, g_h1[p ^ 1], out, d, xs, blockIdx.x);
        gbar();
    }
}

// ---------------------------------------------------------------------------
// Host: ONE launch -> 1 graph node, no multi-node upload buffer.
// ---------------------------------------------------------------------------
extern "C" void kernel_launch(void* const* d_in, const int* in_sizes, int n_in,
                              void* d_out, int out_size) {
    const size_t SMEM = 56064 * sizeof(float);   // 224,256 B <= 227 KB opt-in
    cudaFuncSetAttribute(lstm_persist, cudaFuncAttributeMaxDynamicSharedMemorySize,
                         (int)SMEM);

    lstm_persist<<<NB, 256, SMEM>>>(
        (const float*)d_in[0],
        (const float*)d_in[1],  (const float*)d_in[2],
        (const float*)d_in[3],  (const float*)d_in[4],
        (const float*)d_in[5],  (const float*)d_in[6],
        (const float*)d_in[7],  (const float*)d_in[8],
        (const float*)d_in[9],  (const float*)d_in[10],
        (const float*)d_in[11], (const float*)d_in[12],
        (const float*)d_in[13], (const float*)d_in[14],
        (const float*)d_in[15], (const float*)d_in[16],
        (const float*)d_in[17], (const float*)d_in[18],
        (float*)d_out);
}

// round 7
// speedup vs baseline: 1.1215x; 1.0703x over previous
#include <cuda_runtime.h>
#include <math.h>

// Problem constants
#define HD   512
#define BB   64
#define TT   512
#define FUT  96
#define FF   64
#define NB   128      // persistent CTAs (1/SM, 128 <= 148 -> all co-resident)

typedef unsigned long long u64;

// ---------------------------------------------------------------------------
// Persistent device state. h/c TRANSPOSED [j][b].
// ---------------------------------------------------------------------------
__device__ float g_h0[2][HD * BB];
__device__ float g_h1[2][HD * BB];
__device__ float g_c0[HD * BB];
__device__ float g_c1[HD * BB];
__device__ float g_decx[FF * BB];
__device__ unsigned g_bar_cnt;
__device__ unsigned g_bar_gen;

__device__ __forceinline__ void fma2(u64 &acc, u64 a, u64 b) {
    asm("fma.rn.f32x2 %0, %1, %2, %0;" : "+l"(acc) : "l"(a), "l"(b));
}
__device__ __forceinline__ float unpack_sum(u64 a) {
    float lo, hi;
    asm("mov.b64 {%0,%1}, %2;" : "=f"(lo), "=f"(hi) : "l"(a));
    return lo + hi;
}
__device__ __forceinline__ float sigm(float x) { return 1.0f / (1.0f + expf(-x)); }

// ---------------------------------------------------------------------------
// Grid barrier (sense-reversing). All NB CTAs co-resident -> safe.
// ---------------------------------------------------------------------------
__device__ __forceinline__ void gbar() {
    __syncthreads();
    if (threadIdx.x == 0) {
        unsigned gen = *(volatile unsigned*)&g_bar_gen;
        __threadfence();
        unsigned arrived = atomicAdd(&g_bar_cnt, 1u);
        if (arrived == NB - 1) {
            atomicExch(&g_bar_cnt, 0u);
            __threadfence();
            *(volatile unsigned*)&g_bar_gen = gen + 1u;
        } else {
            while (*(volatile unsigned*)&g_bar_gen == gen) { }
            __threadfence();
        }
    }
    __syncthreads();
}

// ---------------------------------------------------------------------------
// Staging: transposed src [k][64] -> xs[b][k] (row stride 132 floats).
// 128-k chunk: 16 warps, warp w handles k-rows w*8..w*8+7.
// ---------------------------------------------------------------------------
#define XSTR 132

__device__ __forceinline__ void stage_ld128(float2 r[8], const float* __restrict__ src, int k0) {
    int w = threadIdx.x >> 5, lane = threadIdx.x & 31;
    const float* p = src + (size_t)(k0 + w * 8) * 64 + lane * 2;
#pragma unroll
    for (int kk = 0; kk < 8; kk++) r[kk] = *(const float2*)(p + kk * 64);
}
__device__ __forceinline__ void stage_st128(const float2 r[8], float* xs) {
    int w = threadIdx.x >> 5, lane = threadIdx.x & 31;
    int b0 = lane * 2, kb = w * 8;
    *(float4*)(xs + (size_t)b0 * XSTR + kb)           = make_float4(r[0].x, r[1].x, r[2].x, r[3].x);
    *(float4*)(xs + (size_t)b0 * XSTR + kb + 4)       = make_float4(r[4].x, r[5].x, r[6].x, r[7].x);
    *(float4*)(xs + (size_t)(b0 + 1) * XSTR + kb)     = make_float4(r[0].y, r[1].y, r[2].y, r[3].y);
    *(float4*)(xs + (size_t)(b0 + 1) * XSTR + kb + 4) = make_float4(r[4].y, r[5].y, r[6].y, r[7].y);
}
// 64-k chunk: warps 0..7 only.
__device__ __forceinline__ void stage_64(float* xs, const float* __restrict__ src) {
    int w = threadIdx.x >> 5, lane = threadIdx.x & 31;
    if (w < 8) {
        float2 r[8];
        const float* p = src + (size_t)(w * 8) * 64 + lane * 2;
#pragma unroll
        for (int kk = 0; kk < 8; kk++) r[kk] = *(const float2*)(p + kk * 64);
        int b0 = lane * 2, kb = w * 8;
        *(float4*)(xs + (size_t)b0 * XSTR + kb)           = make_float4(r[0].x, r[1].x, r[2].x, r[3].x);
        *(float4*)(xs + (size_t)b0 * XSTR + kb + 4)       = make_float4(r[4].x, r[5].x, r[6].x, r[7].x);
        *(float4*)(xs + (size_t)(b0 + 1) * XSTR + kb)     = make_float4(r[0].y, r[1].y, r[2].y, r[3].y);
        *(float4*)(xs + (size_t)(b0 + 1) * XSTR + kb + 4) = make_float4(r[4].y, r[5].y, r[6].y, r[7].y);
    }
}
// Row-major src (input_seq: row stride TT*FF, 64 floats per b)
__device__ __forceinline__ void stage_R(float* xs, const float* __restrict__ src) {
    for (int i = threadIdx.x; i < 1024; i += 512) {
        int b = i >> 4, q = i & 15;
        float4 v = *(const float4*)(src + (size_t)b * (TT * FF) + q * 4);
        *(float4*)(xs + (size_t)b * XSTR + q * 4) = v;
    }
}

// ---------------------------------------------------------------------------
// Gate accumulation over KC k's. x from smem (8 distinct b per warp -> 1 wf),
// w from smem (4 jj, padded stride -> 1 wf each).
// ---------------------------------------------------------------------------
template<int KC, int GS>
__device__ __forceinline__ void accN(u64 acc[4], const float* x, const float* w) {
#pragma unroll
    for (int k = 0; k < KC; k += 4) {
        ulonglong2 xv = *(const ulonglong2*)(x + k);
        ulonglong2 wv;
        wv = *(const ulonglong2*)(w + k);          fma2(acc[0], xv.x, wv.x); fma2(acc[0], xv.y, wv.y);
        wv = *(const ulonglong2*)(w + GS + k);     fma2(acc[1], xv.x, wv.x); fma2(acc[1], xv.y, wv.y);
        wv = *(const ulonglong2*)(w + 2 * GS + k); fma2(acc[2], xv.x, wv.x); fma2(acc[2], xv.y, wv.y);
        wv = *(const ulonglong2*)(w + 3 * GS + k); fma2(acc[3], xv.x, wv.x); fma2(acc[3], xv.y, wv.y);
    }
}

// K=512 part: 4 chunks of 128, halves take 64 each; prefetch next chunk.
__device__ __forceinline__ void part512(u64 acc[4], const float* __restrict__ src,
                                        const float* W, float* xs, const float* xrow,
                                        int half, int jj) {
    float2 r[8];
    stage_ld128(r, src, 0);
#pragma unroll 1
    for (int c = 0; c < 4; c++) {
        __syncthreads();
        stage_st128(r, xs);
        __syncthreads();
        if (c < 3) stage_ld128(r, src, (c + 1) * 128);
        accN<64, 2064>(acc, xrow + half * 64,
                       W + (size_t)jj * 516 + c * 128 + half * 64);
    }
}

// ---------------------------------------------------------------------------
// Fused LSTM cell (512 threads, split-K halves, combine via smem).
// ---------------------------------------------------------------------------
__device__ __noinline__ void lstm_cell(const float* Wih, int KIN, const float* Whh,
                                       const float* __restrict__ xT,
                                       const float* __restrict__ xR,
                                       const float* __restrict__ hprev,
                                       float* __restrict__ hnext,
                                       float* __restrict__ cbuf,
                                       float* xs, float4 bias,
                                       int b, int jj, int half, int j) {
    u64 acc[4] = {0ull, 0ull, 0ull, 0ull};
    const float* xrow = xs + (size_t)b * XSTR;

    if (KIN == 64) {
        __syncthreads();
        if (xR) stage_R(xs, xR);
        else    stage_64(xs, xT);
        __syncthreads();
        accN<32, 288>(acc, xrow + half * 32, Wih + (size_t)jj * 72 + half * 32);
    } else {
        part512(acc, xT, Wih, xs, xrow, half, jj);
    }
    part512(acc, hprev, Whh, xs, xrow, half, jj);

    // combine halves through smem
    __syncthreads();
    float4 me = make_float4(unpack_sum(acc[0]), unpack_sum(acc[1]),
                            unpack_sum(acc[2]), unpack_sum(acc[3]));
    ((float4*)xs)[threadIdx.x] = me;
    __syncthreads();
    if (half == 0) {
        float4 o = ((float4*)xs)[threadIdx.x + 256];
        float gi = me.x + o.x + bias.x;
        float gf = me.y + o.y + bias.y;
        float gg = me.z + o.z + bias.z;
        float go = me.w + o.w + bias.w;
        int idx = j * 64 + b;
        float c = sigm(gf) * cbuf[idx] + sigm(gi) * tanhf(gg);
        cbuf[idx]  = c;
        hnext[idx] = sigm(go) * tanhf(c);
    }
}

// Decoder FC, CTA f (<64): out[b][d][f] = h1[:,b] . fcrow + fcb[f]
__device__ __noinline__ void fc_step(const float* fcrow, float fcbias,
                                     const float* __restrict__ h1,
                                     float* __restrict__ out, int d,
                                     float* xs, int f) {
    int tid = threadIdx.x, b = tid & 63, q = tid >> 6;   // q: 8-way K split
    u64 acc = 0ull;
    float2 r[8];
    stage_ld128(r, h1, 0);
#pragma unroll 1
    for (int c = 0; c < 4; c++) {
        __syncthreads();
        stage_st128(r, xs);
        __syncthreads();
        if (c < 3) stage_ld128(r, h1, (c + 1) * 128);
        if ((q >> 1) == c) {
            const float* xr = xs + (size_t)b * XSTR + (q & 1) * 64;
            const float* w  = fcrow + q * 64;
#pragma unroll
            for (int k = 0; k < 64; k += 4) {
                ulonglong2 xv = *(const ulonglong2*)(xr + k);
                ulonglong2 wv = *(const ulonglong2*)(w + k);
                fma2(acc, xv.x, wv.x); fma2(acc, xv.y, wv.y);
            }
        }
    }
    __syncthreads();
    xs[q * 64 + b] = unpack_sum(acc);
    __syncthreads();
    if (q == 0) {
        float v = fcbias;
#pragma unroll
        for (int m = 0; m < 8; m++) v += xs[m * 64 + b];
        out[(size_t)b * (FUT * FF) + (size_t)d * FF + f] = v;
        g_decx[f * 64 + b] = v;
    }
}

// Copy 16 weight rows (4 gates x 4 j) with padded row stride RS.
__device__ __forceinline__ void loadW(float* dst, const float* __restrict__ src,
                                      int K, int RS, int j0) {
    int Kq = K >> 2, n = 16 * Kq;
    for (int i = threadIdx.x; i < n; i += 512) {
        int rr = i / Kq, kq = i - rr * Kq;
        int g = rr >> 2, j2 = rr & 3;
        float4 v = *(const float4*)(src + (size_t)(g * HD + j0 + j2) * K + kq * 4);
        *(float4*)(dst + (size_t)rr * RS + kq * 4) = v;
    }
}

// ---------------------------------------------------------------------------
// SMEM map (floats): W0i@0(1152) W0h@1152(8256) W1i@9408(8256) W1h@17664(8256)
//                    fcrow@25920(512) xs@26432(8448)  -> 34880 fl = 139,520 B
// Encoder/decoder weights share buffers (reloaded once between phases).
// ---------------------------------------------------------------------------
__global__ void __launch_bounds__(512, 1)
lstm_persist(const float* __restrict__ in,
             const float* __restrict__ eWih0, const float* __restrict__ eWhh0,
             const float* __restrict__ ebih0, const float* __restrict__ ebhh0,
             const float* __restrict__ eWih1, const float* __restrict__ eWhh1,
             const float* __restrict__ ebih1, const float* __restrict__ ebhh1,
             const float* __restrict__ dWih0, const float* __restrict__ dWhh0,
             const float* __restrict__ dbih0, const float* __restrict__ dbhh0,
             const float* __restrict__ dWih1, const float* __restrict__ dWhh1,
             const float* __restrict__ dbih1, const float* __restrict__ dbhh1,
             const float* __restrict__ fcW,   const float* __restrict__ fcb,
             float* __restrict__ out) {
    extern __shared__ float sm[];
    float* W0i   = sm;
    float* W0h   = sm + 1152;
    float* W1i   = sm + 9408;
    float* W1h   = sm + 17664;
    float* fcrow = sm + 25920;
    float* xs    = sm + 26432;

    const int tid  = threadIdx.x;
    // warp = (half, b_hi): lanes span 4 jj x 8 b_lo  -> x dedup + w conflict-free
    const int half = tid >> 8;
    const int t8   = tid & 255;
    const int b_hi = t8 >> 5;
    const int jj   = (t8 >> 3) & 3;
    const int b_lo = t8 & 7;
    const int b    = b_hi * 8 + b_lo;
    const int j0   = blockIdx.x * 4, j = j0 + jj;

    // encoder weights -> smem
    loadW(W0i, eWih0, 64,  72,  j0);
    loadW(W0h, eWhh0, HD,  516, j0);
    loadW(W1i, eWih1, HD,  516, j0);
    loadW(W1h, eWhh1, HD,  516, j0);
    float fcbias = 0.f;
    if (blockIdx.x < 64) {
        for (int i = tid; i < HD; i += 512) fcrow[i] = fcW[(size_t)blockIdx.x * HD + i];
        fcbias = fcb[blockIdx.x];
    }

    // zero persistent state
    {
        int i = blockIdx.x * 512 + tid;
        if (i < HD * BB) { g_h0[0][i] = 0.f; g_h1[0][i] = 0.f; g_c0[i] = 0.f; g_c1[i] = 0.f; }
        if (i < FF * BB) g_decx[i] = 0.f;
    }

    float4 b_e0 = make_float4(ebih0[j] + ebhh0[j],
                              ebih0[HD + j] + ebhh0[HD + j],
                              ebih0[2 * HD + j] + ebhh0[2 * HD + j],
                              ebih0[3 * HD + j] + ebhh0[3 * HD + j]);
    float4 b_e1 = make_float4(ebih1[j] + ebhh1[j],
                              ebih1[HD + j] + ebhh1[HD + j],
                              ebih1[2 * HD + j] + ebhh1[2 * HD + j],
                              ebih1[3 * HD + j] + ebhh1[3 * HD + j]);
    float4 b_d0 = make_float4(dbih0[j] + dbhh0[j],
                              dbih0[HD + j] + dbhh0[HD + j],
                              dbih0[2 * HD + j] + dbhh0[2 * HD + j],
                              dbih0[3 * HD + j] + dbhh0[3 * HD + j]);
    float4 b_d1 = make_float4(dbih1[j] + dbhh1[j],
                              dbih1[HD + j] + dbhh1[HD + j],
                              dbih1[2 * HD + j] + dbhh1[2 * HD + j],
                              dbih1[3 * HD + j] + dbhh1[3 * HD + j]);

    gbar();

    // ===================== encoder =====================
    lstm_cell(W0i, 64, W0h, nullptr, in, g_h0[0], g_h0[1], g_c0,
              xs, b_e0, b, jj, half, j);
    gbar();
#pragma unroll 1
    for (int t = 0; t < TT - 1; t++) {
        int s = t & 1;
        lstm_cell(W1i, 512, W1h, g_h0[s ^ 1], nullptr, g_h1[s], g_h1[s ^ 1], g_c1,
                  xs, b_e1, b, jj, half, j);
        lstm_cell(W0i, 64, W0h, nullptr, in + (size_t)(t + 1) * FF,
                  g_h0[s ^ 1], g_h0[s], g_c0, xs, b_e0, b, jj, half, j);
        gbar();
    }
    {
        int s = (TT - 1) & 1;   // = 1
        lstm_cell(W1i, 512, W1h, g_h0[s ^ 1], nullptr, g_h1[s], g_h1[s ^ 1], g_c1,
                  xs, b_e1, b, jj, half, j);
    }
    gbar();
    // current h0 = slot 0, h1 = slot 0

    // swap to decoder weights (own smem only; cell's syncthreads orders use)
    loadW(W0i, dWih0, 64,  72,  j0);
    loadW(W0h, dWhh0, HD,  516, j0);
    loadW(W1i, dWih1, HD,  516, j0);
    loadW(W1h, dWhh1, HD,  516, j0);
    __syncthreads();

    // ===================== decoder =====================
#pragma unroll 1
    for (int d = 0; d < FUT; d++) {
        int p = d & 1;
        if (d == 0)
            lstm_cell(W0i, 64, W0h, nullptr, in + (size_t)(TT - 1) * FF,
                      g_h0[p], g_h0[p ^ 1], g_c0, xs, b_d0, b, jj, half, j);
        else
            lstm_cell(W0i, 64, W0h, g_decx, nullptr,
                      g_h0[p], g_h0[p ^ 1], g_c0, xs, b_d0, b, jj, half, j);
        gbar();
        lstm_cell(W1i, 512, W1h, g_h0[p ^ 1], nullptr,
                  g_h1[p], g_h1[p ^ 1], g_c1, xs, b_d1, b, jj, half, j);
        gbar();
        if (blockIdx.x < 64)
            fc_step(fcrow, fcbias, g_h1[p ^ 1], out, d, xs, blockIdx.x);
        gbar();
    }
}

extern "C" void kernel_launch(void* const* d_in, const int* in_sizes, int n_in,
                              void* d_out, int out_size) {
    const size_t SMEM = 34880 * sizeof(float);   // 139,520 B
    cudaFuncSetAttribute(lstm_persist, cudaFuncAttributeMaxDynamicSharedMemorySize,
                         (int)SMEM);
    lstm_persist<<<NB, 512, SMEM>>>(
        (const float*)d_in[0],
        (const float*)d_in[1],  (const float*)d_in[2],
        (const float*)d_in[3],  (const float*)d_in[4],
        (const float*)d_in[5],  (const float*)d_in[6],
        (const float*)d_in[7],  (const float*)d_in[8],
        (const float*)d_in[9],  (const float*)d_in[10],
        (const float*)d_in[11], (const float*)d_in[12],
        (const float*)d_in[13], (const float*)d_in[14],
        (const float*)d_in[15], (const float*)d_in[16],
        (const float*)d_in[17], (const float*)d_in[18],
        (float*)d_out);
}